// round 1
// baseline (speedup 1.0000x reference)
#include <cuda_runtime.h>

#define HH 56
#define WW 56
#define CC 64
#define BB 4
#define HWP 3136           // 56*56
#define NPIX (BB*HWP)      // 12544

// ---------------- scratch (device globals; no allocations) ----------------
__device__ float g_xcl [NPIX*CC];    // x in NHWC
__device__ float g_off3[NPIX*98];    // offset3 in [pix][98]
__device__ float g_off2[NPIX*50];    // offset2 in [pix][50]
__device__ float g_out1[NPIX*CC];    // out1 NHWC
__device__ float g_out2[NPIX*CC];    // out2 NHWC
__device__ float g_w7t [49*CC];      // w7 transposed [k][c]
__device__ float g_w5t [25*CC];      // w5 transposed [k][c]
__device__ float g_part1[BB*32*CC];
__device__ float g_part2[BB*32*CC];
__device__ float g_attn [BB*CC];

// ---------------- tiny weight transpose ----------------
__global__ void k_wtrans(const float* __restrict__ w7, const float* __restrict__ w5) {
    int tid = threadIdx.x;
    for (int i = tid; i < CC*49; i += blockDim.x) {
        int c = i / 49, k = i - c*49;
        g_w7t[k*CC + c] = w7[i];
    }
    for (int i = tid; i < CC*25; i += blockDim.x) {
        int c = i / 25, k = i - c*25;
        g_w5t[k*CC + c] = w5[i];
    }
}

// ---------------- NCHW -> NHWC transpose of x ----------------
__global__ void k_nchw2cl(const float* __restrict__ x) {
    __shared__ float tile[CC][33];
    int b  = blockIdx.x / 98;
    int p0 = (blockIdx.x % 98) * 32;
    int tid = threadIdx.x;
#pragma unroll
    for (int it = 0; it < 8; it++) {
        int idx = tid + it*256;
        int c = idx >> 5, pp = idx & 31;
        tile[c][pp] = x[((size_t)(b*CC + c))*HWP + p0 + pp];
    }
    __syncthreads();
    int c2 = tid & 63;
#pragma unroll
    for (int it = 0; it < 8; it++) {
        int pp2 = (tid >> 6) + it*4;
        g_xcl[((size_t)(b*HWP + p0 + pp2))*CC + c2] = tile[c2][pp2];
    }
}

// ---------------- grouped 3x3 conv (groups=2), reads NHWC x ----------------
// block: one (b, y, x-tile of 14). thread = output channel.
template<int OUTC, int NT>
__global__ void k_conv3x3_g2(const float* __restrict__ xcl,
                             const float* __restrict__ w,
                             const float* __restrict__ bias,
                             float* __restrict__ out) {
    __shared__ float xs[3][16][CC];
    int bid = blockIdx.x;
    int xt = bid & 3;
    int y  = (bid >> 2) % HH;
    int b  = bid / (4*HH);
    int x0 = xt * 14;
    int tid = threadIdx.x;

    for (int i = tid; i < 3*16*CC; i += NT) {
        int c   = i & 63;
        int col = (i >> 6) & 15;
        int dy  = i >> 10;
        int yy = y + dy - 1;
        int xx = x0 + col - 1;
        float v = 0.f;
        if (yy >= 0 && yy < HH && xx >= 0 && xx < WW)
            v = xcl[((size_t)((b*HH + yy)*WW + xx))*CC + c];
        xs[dy][col][c] = v;
    }
    __syncthreads();

    int o = tid;
    if (o < OUTC) {
        const int half = OUTC/2;
        int cbase = (o < half) ? 0 : 32;
        float acc[14];
        float bo = bias[o];
#pragma unroll
        for (int p = 0; p < 14; p++) acc[p] = bo;

        for (int ic = 0; ic < 32; ic++) {
            float w9[9];
#pragma unroll
            for (int j = 0; j < 9; j++)
                w9[j] = __ldg(&w[(o*32 + ic)*9 + j]);
#pragma unroll
            for (int dy = 0; dy < 3; dy++) {
                float xr[16];
#pragma unroll
                for (int col = 0; col < 16; col++)
                    xr[col] = xs[dy][col][cbase + ic];
#pragma unroll
                for (int dx = 0; dx < 3; dx++) {
#pragma unroll
                    for (int p = 0; p < 14; p++)
                        acc[p] = fmaf(w9[dy*3+dx], xr[p+dx], acc[p]);
                }
            }
        }
        size_t pix = (size_t)(b*HH + y)*WW + x0;
#pragma unroll
        for (int p = 0; p < 14; p++)
            out[(pix + p)*OUTC + o] = acc[p];
    }
}

// ---------------- deformable depthwise conv ----------------
// 128 threads = 4 warps; each warp owns one pixel; lane owns channel pair (2l,2l+1).
template<int K, int PAD, int DIL>
__global__ void k_deform(const float* __restrict__ src,   // NHWC
                         const float* __restrict__ off,   // [pix][2*K*K]
                         const float* __restrict__ wt,    // [K*K][C]
                         const float* __restrict__ bias,
                         float* __restrict__ out) {       // NHWC
    constexpr int K2 = K*K;
    constexpr int OFFC = 2*K2;
    __shared__ float soff[4][OFFC];
    int wid  = threadIdx.x >> 5;
    int lane = threadIdx.x & 31;
    int gp = blockIdx.x*4 + wid;

    for (int j = lane; j < OFFC; j += 32)
        soff[wid][j] = off[(size_t)gp*OFFC + j];
    __syncwarp();

    int b = gp / HWP;
    int p = gp - b*HWP;
    int y = p / WW;
    int x = p - y*WW;
    const float* sb = src + (size_t)b*HWP*CC;
    int c2 = lane*2;

    float2 acc = *(const float2*)(bias + c2);

    for (int ky = 0; ky < K; ky++) {
        float by = (float)(y - PAD + DIL*ky);
#pragma unroll
        for (int kx = 0; kx < K; kx++) {
            int k = ky*K + kx;
            float py = by + soff[wid][2*k];
            float px = (float)(x - PAD + DIL*kx) + soff[wid][2*k+1];
            float fy = floorf(py), fx = floorf(px);
            float ly = py - fy,  lx = px - fx;
            float hy = 1.f - ly, hx = 1.f - lx;
            int iy0 = (int)fy, ix0 = (int)fx;
            int iy1 = iy0 + 1, ix1 = ix0 + 1;
            bool vy0 = (iy0 >= 0) && (iy0 < HH);
            bool vy1 = (iy1 >= 0) && (iy1 < HH);
            bool vx0 = (ix0 >= 0) && (ix0 < WW);
            bool vx1 = (ix1 >= 0) && (ix1 < WW);
            float c00 = (vy0 && vx0) ? hy*hx : 0.f;
            float c01 = (vy0 && vx1) ? hy*lx : 0.f;
            float c10 = (vy1 && vx0) ? ly*hx : 0.f;
            float c11 = (vy1 && vx1) ? ly*lx : 0.f;
            int jy0 = min(max(iy0,0), HH-1), jy1 = min(max(iy1,0), HH-1);
            int jx0 = min(max(ix0,0), WW-1), jx1 = min(max(ix1,0), WW-1);
            const float* r0 = sb + (size_t)(jy0*WW)*CC;
            const float* r1 = sb + (size_t)(jy1*WW)*CC;
            float2 v00 = *(const float2*)(r0 + jx0*CC + c2);
            float2 v01 = *(const float2*)(r0 + jx1*CC + c2);
            float2 v10 = *(const float2*)(r1 + jx0*CC + c2);
            float2 v11 = *(const float2*)(r1 + jx1*CC + c2);
            float valx = c00*v00.x + c01*v01.x + c10*v10.x + c11*v11.x;
            float valy = c00*v00.y + c01*v01.y + c10*v10.y + c11*v11.y;
            float2 wv = *(const float2*)(wt + k*CC + c2);
            acc.x = fmaf(wv.x, valx, acc.x);
            acc.y = fmaf(wv.y, valy, acc.y);
        }
    }
    *(float2*)(out + (size_t)gp*CC + c2) = acc;
}

// ---------------- GAP partial sums ----------------
__global__ void k_gap_part() {
    int b = blockIdx.x >> 5;
    int chunk = blockIdx.x & 31;
    int c = threadIdx.x;
    float s1 = 0.f, s2 = 0.f;
    int p0 = chunk * 98;
    for (int p = 0; p < 98; p++) {
        size_t idx = ((size_t)(b*HWP + p0 + p))*CC + c;
        s1 += g_out1[idx];
        s2 += g_out2[idx];
    }
    g_part1[(b*32 + chunk)*CC + c] = s1;
    g_part2[(b*32 + chunk)*CC + c] = s2;
}

// ---------------- GAP finalize + softmax attn ----------------
__global__ void k_gap_final() {
    int b = blockIdx.x;
    int c = threadIdx.x;
    float s1 = 0.f, s2 = 0.f;
    for (int j = 0; j < 32; j++) {
        s1 += g_part1[(b*32 + j)*CC + c];
        s2 += g_part2[(b*32 + j)*CC + c];
    }
    float g1 = s1 * (1.f/3136.f), g2 = s2 * (1.f/3136.f);
    float m = fmaxf(g1, g2);
    float e1 = expf(g1 - m), e2 = expf(g2 - m);
    g_attn[b*CC + c] = e1 / (e1 + e2);
}

// ---------------- combine + NHWC -> NCHW ----------------
__global__ void k_combine(float* __restrict__ out) {
    __shared__ float tile[CC][33];
    int b  = blockIdx.x / 98;
    int p0 = (blockIdx.x % 98) * 32;
    int tid = threadIdx.x;
    int c = tid & 63;
    float a = g_attn[b*CC + c];
#pragma unroll
    for (int it = 0; it < 8; it++) {
        int pp = (tid >> 6) + it*4;
        size_t idx = ((size_t)(b*HWP + p0 + pp))*CC + c;
        float v1 = g_out1[idx], v2 = g_out2[idx];
        tile[c][pp] = v1*a + v2*(1.f - a);
    }
    __syncthreads();
#pragma unroll
    for (int it = 0; it < 8; it++) {
        int idx = tid + it*256;
        int cc = idx >> 5, pp = idx & 31;
        out[((size_t)(b*CC + cc))*HWP + p0 + pp] = tile[cc][pp];
    }
}

// ---------------- launcher ----------------
extern "C" void kernel_launch(void* const* d_in, const int* in_sizes, int n_in,
                              void* d_out, int out_size) {
    const float* x      = (const float*)d_in[0];
    const float* w_off3 = (const float*)d_in[1];
    const float* b_off3 = (const float*)d_in[2];
    const float* w_off2 = (const float*)d_in[3];
    const float* b_off2 = (const float*)d_in[4];
    const float* w7     = (const float*)d_in[5];
    const float* b7     = (const float*)d_in[6];
    const float* w5     = (const float*)d_in[7];
    const float* b5     = (const float*)d_in[8];
    float* out = (float*)d_out;

    float *p_xcl, *p_off3, *p_off2, *p_out1, *p_out2, *p_w7t, *p_w5t;
    cudaGetSymbolAddress((void**)&p_xcl,  g_xcl);
    cudaGetSymbolAddress((void**)&p_off3, g_off3);
    cudaGetSymbolAddress((void**)&p_off2, g_off2);
    cudaGetSymbolAddress((void**)&p_out1, g_out1);
    cudaGetSymbolAddress((void**)&p_out2, g_out2);
    cudaGetSymbolAddress((void**)&p_w7t,  g_w7t);
    cudaGetSymbolAddress((void**)&p_w5t,  g_w5t);

    k_wtrans<<<1, 256>>>(w7, w5);
    k_nchw2cl<<<BB*98, 256>>>(x);

    k_conv3x3_g2<98,128><<<BB*HH*4, 128>>>(p_xcl, w_off3, b_off3, p_off3);
    k_conv3x3_g2<50, 64><<<BB*HH*4,  64>>>(p_xcl, w_off2, b_off2, p_off2);

    k_deform<7,9,3><<<NPIX/4, 128>>>(p_xcl,  p_off3, p_w7t, b7, p_out1);
    k_deform<5,6,3><<<NPIX/4, 128>>>(p_out1, p_off2, p_w5t, b5, p_out2);

    k_gap_part<<<BB*32, 64>>>();
    k_gap_final<<<BB, 64>>>();
    k_combine<<<BB*98, 256>>>(out);
}

// round 2
// speedup vs baseline: 1.9862x; 1.9862x over previous
#include <cuda_runtime.h>

#define HH 56
#define WW 56
#define CC 64
#define BB 4
#define HWP 3136           // 56*56
#define NPIX (BB*HWP)      // 12544
#define OCOMB 160          // padded combined output channels (98 + 50 -> 148 -> 160)

// ---------------- scratch (device globals; no allocations) ----------------
__device__ float g_xcl [NPIX*CC];      // x in NHWC
__device__ float g_off3[NPIX*98];      // offset3 [pix][98]
__device__ float g_off2[NPIX*50];      // offset2 [pix][50]
__device__ float g_out1[NPIX*CC];      // out1 NHWC
__device__ float g_out2[NPIX*CC];      // out2 NHWC
__device__ float g_w7t [49*CC];        // w7 transposed [k][c]
__device__ float g_w5t [25*CC];        // w5 transposed [k][c]
__device__ float g_wcomb[288*OCOMB];   // combined conv weights [(ic*9+j)][o]
__device__ float g_bcomb[OCOMB];       // combined conv bias
__device__ float g_part1[BB*32*CC];
__device__ float g_part2[BB*32*CC];
__device__ float g_attn [BB*CC];

// ---------------- weight prep: deform transposes + combined conv table ----
__global__ void k_wprep(const float* __restrict__ w7, const float* __restrict__ w5,
                        const float* __restrict__ w_off3, const float* __restrict__ b_off3,
                        const float* __restrict__ w_off2, const float* __restrict__ b_off2) {
    int tid = threadIdx.x;
    for (int i = tid; i < CC*49; i += blockDim.x) {
        int c = i / 49, k = i - c*49;
        g_w7t[k*CC + c] = w7[i];
    }
    for (int i = tid; i < CC*25; i += blockDim.x) {
        int c = i / 25, k = i - c*25;
        g_w5t[k*CC + c] = w5[i];
    }
    // combined conv weights: row r = ic*9+j, col o
    for (int i = tid; i < 288*OCOMB; i += blockDim.x) {
        int r = i / OCOMB, o = i - r*OCOMB;
        int ic = r / 9, j = r - ic*9;
        float v = 0.f;
        if (o < 98)        v = w_off3[(o*32 + ic)*9 + j];
        else if (o < 148)  v = w_off2[((o-98)*32 + ic)*9 + j];
        g_wcomb[i] = v;
    }
    for (int o = tid; o < OCOMB; o += blockDim.x) {
        float v = 0.f;
        if (o < 98)       v = b_off3[o];
        else if (o < 148) v = b_off2[o-98];
        g_bcomb[o] = v;
    }
}

// ---------------- NCHW -> NHWC transpose of x ----------------
__global__ void k_nchw2cl(const float* __restrict__ x) {
    __shared__ float tile[CC][33];
    int b  = blockIdx.x / 98;
    int p0 = (blockIdx.x % 98) * 32;
    int tid = threadIdx.x;
#pragma unroll
    for (int it = 0; it < 8; it++) {
        int idx = tid + it*256;
        int c = idx >> 5, pp = idx & 31;
        tile[c][pp] = x[((size_t)(b*CC + c))*HWP + p0 + pp];
    }
    __syncthreads();
    int c2 = tid & 63;
#pragma unroll
    for (int it = 0; it < 8; it++) {
        int pp2 = (tid >> 6) + it*4;
        g_xcl[((size_t)(b*HWP + p0 + pp2))*CC + c2] = tile[c2][pp2];
    }
}

// ---------------- fused grouped 3x3 convs (both offset convs) -------------
// block = (b, y, x-tile of 14); thread = combined output channel (160).
// x tile smem layout [dy][c][col(pad 20)] -> broadcast LDS.128 reads.
__global__ __launch_bounds__(OCOMB) void k_conv_fused(const float* __restrict__ xcl,
                                                      float* __restrict__ out3,
                                                      float* __restrict__ out2) {
    __shared__ float xs[3][CC][20];
    int bid = blockIdx.x;
    int xt = bid & 3;
    int y  = (bid >> 2) % HH;
    int b  = bid / (4*HH);
    int x0 = xt * 14;
    int tid = threadIdx.x;

    // stage x tile (rows y-1..y+1, cols x0-1..x0+14), zero padded
    for (int i = tid; i < 3*16*CC; i += OCOMB) {
        int c   = i & 63;
        int col = (i >> 6) & 15;
        int dy  = i >> 10;
        int yy = y + dy - 1;
        int xx = x0 + col - 1;
        float v = 0.f;
        if (yy >= 0 && yy < HH && xx >= 0 && xx < WW)
            v = xcl[((size_t)((b*HH + yy)*WW + xx))*CC + c];
        xs[dy][c][col] = v;
    }
    // zero padding cols 16..19 (avoid garbage in float4 reads)
    for (int i = tid; i < 3*CC*4; i += OCOMB) {
        int c  = (i >> 2) & 63;
        int dy = i >> 8;
        xs[dy][c][16 + (i & 3)] = 0.f;
    }
    __syncthreads();

    int o = tid;
    bool is3 = (o < 98);
    int oc   = is3 ? o : o - 98;
    int half = is3 ? 49 : 25;
    int cbase = (oc < half) ? 0 : 32;

    float acc[14];
    float bo = g_bcomb[o];
#pragma unroll
    for (int p = 0; p < 14; p++) acc[p] = bo;

    const float* wp = g_wcomb + o;
#pragma unroll 4
    for (int ic = 0; ic < 32; ic++) {
        float w9[9];
#pragma unroll
        for (int j = 0; j < 9; j++)
            w9[j] = wp[(ic*9 + j)*OCOMB];
#pragma unroll
        for (int dy = 0; dy < 3; dy++) {
            const float4* xrow = (const float4*)&xs[dy][cbase + ic][0];
            float xr[16];
            float4 t0 = xrow[0], t1 = xrow[1], t2 = xrow[2], t3 = xrow[3];
            xr[0]=t0.x; xr[1]=t0.y; xr[2]=t0.z; xr[3]=t0.w;
            xr[4]=t1.x; xr[5]=t1.y; xr[6]=t1.z; xr[7]=t1.w;
            xr[8]=t2.x; xr[9]=t2.y; xr[10]=t2.z; xr[11]=t2.w;
            xr[12]=t3.x; xr[13]=t3.y; xr[14]=t3.z; xr[15]=t3.w;
#pragma unroll
            for (int dx = 0; dx < 3; dx++) {
                float wv = w9[dy*3 + dx];
#pragma unroll
                for (int p = 0; p < 14; p++)
                    acc[p] = fmaf(wv, xr[p+dx], acc[p]);
            }
        }
    }

    size_t pix = (size_t)(b*HH + y)*WW + x0;
    if (is3) {
#pragma unroll
        for (int p = 0; p < 14; p++)
            out3[(pix + p)*98 + o] = acc[p];
    } else if (o < 148) {
        int o2 = o - 98;
#pragma unroll
        for (int p = 0; p < 14; p++)
            out2[(pix + p)*50 + o2] = acc[p];
    }
}

// ---------------- deformable depthwise conv (2-phase) ----------------
// 128 threads = 4 warps; each warp owns one pixel; lane owns channel pair.
// Phase 1: lanes compute per-tap bilinear coefs + element offsets into smem.
// Phase 2: taps replay as broadcast LDS + 4 coalesced LDG.64 + FMAs.
template<int K, int PAD, int DIL>
__global__ void k_deform(const float* __restrict__ src,   // NHWC
                         const float* __restrict__ off,   // [pix][2*K*K]
                         const float* __restrict__ wt,    // [K*K][C]
                         const float* __restrict__ bias,
                         float* __restrict__ out) {       // NHWC
    constexpr int K2 = K*K;
    constexpr int OFFC = 2*K2;
    __shared__ float4 scoef[4][K2];
    __shared__ int4   saddr[4][K2];
    int wid  = threadIdx.x >> 5;
    int lane = threadIdx.x & 31;
    int gp = blockIdx.x*4 + wid;

    int b = gp / HWP;
    int p = gp - b*HWP;
    int y = p / WW;
    int x = p - y*WW;

    // phase 1: per-tap coefficient + address precompute
    {
        int t = lane;
#pragma unroll
        for (int r = 0; r < (K2 + 31)/32; r++, t += 32) {
            if (t < K2) {
                float2 o2 = *(const float2*)(off + (size_t)gp*OFFC + 2*t);
                int ky = t / K, kx = t - ky*K;
                float py = (float)(y - PAD + DIL*ky) + o2.x;
                float px = (float)(x - PAD + DIL*kx) + o2.y;
                float fy = floorf(py), fx = floorf(px);
                float ly = py - fy,  lx = px - fx;
                float hy = 1.f - ly, hx = 1.f - lx;
                int iy0 = (int)fy, ix0 = (int)fx;
                int iy1 = iy0 + 1, ix1 = ix0 + 1;
                bool vy0 = (unsigned)iy0 < HH;
                bool vy1 = (unsigned)iy1 < HH;
                bool vx0 = (unsigned)ix0 < WW;
                bool vx1 = (unsigned)ix1 < WW;
                float c00 = (vy0 && vx0) ? hy*hx : 0.f;
                float c01 = (vy0 && vx1) ? hy*lx : 0.f;
                float c10 = (vy1 && vx0) ? ly*hx : 0.f;
                float c11 = (vy1 && vx1) ? ly*lx : 0.f;
                int jy0 = min(max(iy0,0), HH-1), jy1 = min(max(iy1,0), HH-1);
                int jx0 = min(max(ix0,0), WW-1), jx1 = min(max(ix1,0), WW-1);
                scoef[wid][t] = make_float4(c00, c01, c10, c11);
                saddr[wid][t] = make_int4((jy0*WW + jx0)*CC, (jy0*WW + jx1)*CC,
                                          (jy1*WW + jx0)*CC, (jy1*WW + jx1)*CC);
            }
        }
    }
    __syncwarp();

    const float* sb = src + (size_t)b*HWP*CC;
    int c2 = lane*2;
    float2 acc = *(const float2*)(bias + c2);

#pragma unroll
    for (int k = 0; k < K2; k++) {
        float4 cf = scoef[wid][k];
        int4  ad = saddr[wid][k];
        float2 v00 = *(const float2*)(sb + ad.x + c2);
        float2 v01 = *(const float2*)(sb + ad.y + c2);
        float2 v10 = *(const float2*)(sb + ad.z + c2);
        float2 v11 = *(const float2*)(sb + ad.w + c2);
        float vx = cf.x*v00.x + cf.y*v01.x + cf.z*v10.x + cf.w*v11.x;
        float vy = cf.x*v00.y + cf.y*v01.y + cf.z*v10.y + cf.w*v11.y;
        float2 wv = *(const float2*)(wt + k*CC + c2);
        acc.x = fmaf(wv.x, vx, acc.x);
        acc.y = fmaf(wv.y, vy, acc.y);
    }
    *(float2*)(out + (size_t)gp*CC + c2) = acc;
}

// ---------------- GAP partial sums ----------------
__global__ void k_gap_part() {
    int b = blockIdx.x >> 5;
    int chunk = blockIdx.x & 31;
    int c = threadIdx.x;
    float s1 = 0.f, s2 = 0.f;
    int p0 = chunk * 98;
    for (int p = 0; p < 98; p++) {
        size_t idx = ((size_t)(b*HWP + p0 + p))*CC + c;
        s1 += g_out1[idx];
        s2 += g_out2[idx];
    }
    g_part1[(b*32 + chunk)*CC + c] = s1;
    g_part2[(b*32 + chunk)*CC + c] = s2;
}

// ---------------- GAP finalize + softmax attn ----------------
__global__ void k_gap_final() {
    int b = blockIdx.x;
    int c = threadIdx.x;
    float s1 = 0.f, s2 = 0.f;
    for (int j = 0; j < 32; j++) {
        s1 += g_part1[(b*32 + j)*CC + c];
        s2 += g_part2[(b*32 + j)*CC + c];
    }
    float g1 = s1 * (1.f/3136.f), g2 = s2 * (1.f/3136.f);
    float m = fmaxf(g1, g2);
    float e1 = expf(g1 - m), e2 = expf(g2 - m);
    g_attn[b*CC + c] = e1 / (e1 + e2);
}

// ---------------- combine + NHWC -> NCHW ----------------
__global__ void k_combine(float* __restrict__ out) {
    __shared__ float tile[CC][33];
    int b  = blockIdx.x / 98;
    int p0 = (blockIdx.x % 98) * 32;
    int tid = threadIdx.x;
    int c = tid & 63;
    float a = g_attn[b*CC + c];
#pragma unroll
    for (int it = 0; it < 8; it++) {
        int pp = (tid >> 6) + it*4;
        size_t idx = ((size_t)(b*HWP + p0 + pp))*CC + c;
        float v1 = g_out1[idx], v2 = g_out2[idx];
        tile[c][pp] = v1*a + v2*(1.f - a);
    }
    __syncthreads();
#pragma unroll
    for (int it = 0; it < 8; it++) {
        int idx = tid + it*256;
        int cc = idx >> 5, pp = idx & 31;
        out[((size_t)(b*CC + cc))*HWP + p0 + pp] = tile[cc][pp];
    }
}

// ---------------- launcher ----------------
extern "C" void kernel_launch(void* const* d_in, const int* in_sizes, int n_in,
                              void* d_out, int out_size) {
    const float* x      = (const float*)d_in[0];
    const float* w_off3 = (const float*)d_in[1];
    const float* b_off3 = (const float*)d_in[2];
    const float* w_off2 = (const float*)d_in[3];
    const float* b_off2 = (const float*)d_in[4];
    const float* w7     = (const float*)d_in[5];
    const float* b7     = (const float*)d_in[6];
    const float* w5     = (const float*)d_in[7];
    const float* b5     = (const float*)d_in[8];
    float* out = (float*)d_out;

    float *p_xcl, *p_off3, *p_off2, *p_out1, *p_out2, *p_w7t, *p_w5t;
    cudaGetSymbolAddress((void**)&p_xcl,  g_xcl);
    cudaGetSymbolAddress((void**)&p_off3, g_off3);
    cudaGetSymbolAddress((void**)&p_off2, g_off2);
    cudaGetSymbolAddress((void**)&p_out1, g_out1);
    cudaGetSymbolAddress((void**)&p_out2, g_out2);
    cudaGetSymbolAddress((void**)&p_w7t,  g_w7t);
    cudaGetSymbolAddress((void**)&p_w5t,  g_w5t);

    k_wprep<<<1, 256>>>(w7, w5, w_off3, b_off3, w_off2, b_off2);
    k_nchw2cl<<<BB*98, 256>>>(x);

    k_conv_fused<<<BB*HH*4, OCOMB>>>(p_xcl, p_off3, p_off2);

    k_deform<7,9,3><<<NPIX/4, 128>>>(p_xcl,  p_off3, p_w7t, b7, p_out1);
    k_deform<5,6,3><<<NPIX/4, 128>>>(p_out1, p_off2, p_w5t, b5, p_out2);

    k_gap_part<<<BB*32, 64>>>();
    k_gap_final<<<BB, 64>>>();
    k_combine<<<BB*98, 256>>>(out);
}

// round 3
// speedup vs baseline: 2.0111x; 1.0125x over previous
#include <cuda_runtime.h>

#define HH 56
#define WW 56
#define CC 64
#define BB 4
#define HWP 3136           // 56*56
#define NPIX (BB*HWP)      // 12544

// ---------------- packed f32x2 helpers ----------------
__device__ __forceinline__ unsigned long long fma2(unsigned long long a, unsigned long long b, unsigned long long c) {
    unsigned long long d;
    asm("fma.rn.f32x2 %0, %1, %2, %3;" : "=l"(d) : "l"(a), "l"(b), "l"(c));
    return d;
}
__device__ __forceinline__ unsigned long long mul2(unsigned long long a, unsigned long long b) {
    unsigned long long d;
    asm("mul.rn.f32x2 %0, %1, %2;" : "=l"(d) : "l"(a), "l"(b));
    return d;
}

// ---------------- scratch (device globals; no allocations) ----------------
__device__ __align__(16) float g_xcl [NPIX*CC];      // x in NHWC
__device__ __align__(16) float g_off3[NPIX*98];      // offset3 [pix][98]
__device__ __align__(16) float g_off2[NPIX*50];      // offset2 [pix][50]
__device__ __align__(16) float g_out1[NPIX*CC];      // out1 NHWC
__device__ __align__(16) float g_out2[NPIX*CC];      // out2 NHWC
__device__ __align__(16) float g_w7t [49*CC];        // w7 transposed [k][c]
__device__ __align__(16) float g_w5t [25*CC];        // w5 transposed [k][c]
__device__ __align__(16) float2 g_wp3[288*49];       // conv3 weight pairs [(ic*9+j)][o]: (w_o, w_{o+49})
__device__ __align__(16) float2 g_wp2[288*25];       // conv2 weight pairs
__device__ __align__(16) float2 g_bp3[49];
__device__ __align__(16) float2 g_bp2[25];
__device__ __align__(16) float g_part1[BB*32*CC];
__device__ __align__(16) float g_part2[BB*32*CC];
__device__ __align__(16) float g_attn [BB*CC];

// ---------------- weight prep ----------------
__global__ void k_wprep(const float* __restrict__ w7, const float* __restrict__ w5,
                        const float* __restrict__ w_off3, const float* __restrict__ b_off3,
                        const float* __restrict__ w_off2, const float* __restrict__ b_off2) {
    int tid = threadIdx.x;
    for (int i = tid; i < CC*49; i += blockDim.x) {
        int c = i / 49, k = i - c*49;
        g_w7t[k*CC + c] = w7[i];
    }
    for (int i = tid; i < CC*25; i += blockDim.x) {
        int c = i / 25, k = i - c*25;
        g_w5t[k*CC + c] = w5[i];
    }
    for (int i = tid; i < 288*49; i += blockDim.x) {
        int r = i / 49, o = i - r*49;
        int ic = r / 9, j = r - ic*9;
        g_wp3[i] = make_float2(w_off3[(o*32 + ic)*9 + j], w_off3[((o+49)*32 + ic)*9 + j]);
    }
    for (int i = tid; i < 288*25; i += blockDim.x) {
        int r = i / 25, o = i - r*25;
        int ic = r / 9, j = r - ic*9;
        g_wp2[i] = make_float2(w_off2[(o*32 + ic)*9 + j], w_off2[((o+25)*32 + ic)*9 + j]);
    }
    if (tid < 49) g_bp3[tid] = make_float2(b_off3[tid], b_off3[tid+49]);
    if (tid < 25) g_bp2[tid] = make_float2(b_off2[tid], b_off2[tid+25]);
}

// ---------------- NCHW -> NHWC transpose of x ----------------
__global__ void k_nchw2cl(const float* __restrict__ x) {
    __shared__ float tile[CC][33];
    int b  = blockIdx.x / 98;
    int p0 = (blockIdx.x % 98) * 32;
    int tid = threadIdx.x;
#pragma unroll
    for (int it = 0; it < 8; it++) {
        int idx = tid + it*256;
        int c = idx >> 5, pp = idx & 31;
        tile[c][pp] = x[((size_t)(b*CC + c))*HWP + p0 + pp];
    }
    __syncthreads();
    int c2 = tid & 63;
#pragma unroll
    for (int it = 0; it < 8; it++) {
        int pp2 = (tid >> 6) + it*4;
        g_xcl[((size_t)(b*HWP + p0 + pp2))*CC + c2] = tile[c2][pp2];
    }
}

// ---------------- fused grouped 3x3 convs, channel-pair f32x2 -------------
// block = (b, y, x-tile of 14); 96 threads. Thread t<49: conv3 pair (t, t+49);
// 49<=t<74: conv2 pair (t-49, t-24). x tile staged as (group0,group1) float2 pairs.
__global__ __launch_bounds__(96) void k_conv_fused(const float* __restrict__ xcl,
                                                   float* __restrict__ out3,
                                                   float* __restrict__ out2) {
    __shared__ float2 xsp[3][16][32];   // [dy][col][ic]: (x[ic], x[ic+32])
    int bid = blockIdx.x;
    int xt = bid & 3;
    int y  = (bid >> 2) % HH;
    int b  = bid / (4*HH);
    int x0 = xt * 14;
    int tid = threadIdx.x;

    // stage: 3*16*32 = 1536 pairs, 16 iters of coalesced dual loads
#pragma unroll
    for (int it = 0; it < 16; it++) {
        int i = tid + it*96;
        int ic  = i & 31;
        int col = (i >> 5) & 15;
        int dy  = i >> 9;
        int yy = y + dy - 1;
        int xx = x0 + col - 1;
        float v0 = 0.f, v1 = 0.f;
        if (yy >= 0 && yy < HH && xx >= 0 && xx < WW) {
            size_t base = ((size_t)((b*HH + yy)*WW + xx))*CC;
            v0 = xcl[base + ic];
            v1 = xcl[base + 32 + ic];
        }
        xsp[dy][col][ic] = make_float2(v0, v1);
    }
    __syncthreads();

    int t = tid;
    if (t < 74) {
        bool is3 = (t < 49);
        int o = is3 ? t : t - 49;
        int stride = is3 ? 49 : 25;
        const unsigned long long* wrow = is3 ? ((const unsigned long long*)g_wp3) + o
                                             : ((const unsigned long long*)g_wp2) + o;
        float2 bp = is3 ? g_bp3[o] : g_bp2[o];
        unsigned long long bdup;
        asm("mov.b64 %0, {%1, %2};" : "=l"(bdup) : "f"(bp.x), "f"(bp.y));

        unsigned long long acc[14];
#pragma unroll
        for (int p = 0; p < 14; p++) acc[p] = bdup;

#pragma unroll 2
        for (int ic = 0; ic < 32; ic++) {
            unsigned long long w2[9];
#pragma unroll
            for (int j = 0; j < 9; j++)
                w2[j] = wrow[(ic*9 + j)*stride];
#pragma unroll
            for (int dy = 0; dy < 3; dy++) {
                unsigned long long xm[16];
#pragma unroll
                for (int col = 0; col < 16; col++)
                    xm[col] = *(const unsigned long long*)&xsp[dy][col][ic];
#pragma unroll
                for (int dx = 0; dx < 3; dx++) {
                    unsigned long long wv = w2[dy*3 + dx];
#pragma unroll
                    for (int p = 0; p < 14; p++)
                        acc[p] = fma2(wv, xm[p+dx], acc[p]);
                }
            }
        }

        size_t pix = (size_t)(b*HH + y)*WW + x0;
        union { unsigned long long u; float f[2]; } cv;
        if (is3) {
#pragma unroll
            for (int p = 0; p < 14; p++) {
                cv.u = acc[p];
                out3[(pix + p)*98 + o]      = cv.f[0];
                out3[(pix + p)*98 + o + 49] = cv.f[1];
            }
        } else {
#pragma unroll
            for (int p = 0; p < 14; p++) {
                cv.u = acc[p];
                out2[(pix + p)*50 + o]      = cv.f[0];
                out2[(pix + p)*50 + o + 25] = cv.f[1];
            }
        }
    }
}

// ---------------- deformable depthwise conv ----------------
// 128 threads = 4 warps; each warp owns TWO pixels (half-warp each);
// lane owns 4 channels. Coefs pre-duplicated for f32x2 math.
template<int K, int PAD, int DIL>
__global__ void k_deform(const float* __restrict__ src,   // NHWC
                         const float* __restrict__ off,   // [pix][2*K*K]
                         const float* __restrict__ wt,    // [K*K][C]
                         const float* __restrict__ bias,
                         float* __restrict__ out) {       // NHWC
    constexpr int K2 = K*K;
    constexpr int OFFC = 2*K2;
    __shared__ float4 scoef[4][2][K2][2];  // {c00,c00,c01,c01},{c10,c10,c11,c11}
    __shared__ int4   saddr[4][2][K2];
    int wid  = threadIdx.x >> 5;
    int lane = threadIdx.x & 31;
    int gp0 = blockIdx.x*8 + wid*2;

    // phase 1: per-tap coefficient + address precompute for both pixels
    for (int tpos = lane; tpos < 2*K2; tpos += 32) {
        int pl = tpos / K2;
        int k  = tpos - pl*K2;
        int gp = gp0 + pl;
        int b = gp / HWP;
        int p = gp - b*HWP;
        int y = p / WW;
        int x = p - y*WW;
        float2 o2 = *(const float2*)(off + (size_t)gp*OFFC + 2*k);
        int ky = k / K, kx = k - ky*K;
        float py = (float)(y - PAD + DIL*ky) + o2.x;
        float px = (float)(x - PAD + DIL*kx) + o2.y;
        float fy = floorf(py), fx = floorf(px);
        float ly = py - fy,  lx = px - fx;
        float hy = 1.f - ly, hx = 1.f - lx;
        int iy0 = (int)fy, ix0 = (int)fx;
        int iy1 = iy0 + 1, ix1 = ix0 + 1;
        bool vy0 = (unsigned)iy0 < HH;
        bool vy1 = (unsigned)iy1 < HH;
        bool vx0 = (unsigned)ix0 < WW;
        bool vx1 = (unsigned)ix1 < WW;
        float c00 = (vy0 && vx0) ? hy*hx : 0.f;
        float c01 = (vy0 && vx1) ? hy*lx : 0.f;
        float c10 = (vy1 && vx0) ? ly*hx : 0.f;
        float c11 = (vy1 && vx1) ? ly*lx : 0.f;
        int jy0 = min(max(iy0,0), HH-1), jy1 = min(max(iy1,0), HH-1);
        int jx0 = min(max(ix0,0), WW-1), jx1 = min(max(ix1,0), WW-1);
        scoef[wid][pl][k][0] = make_float4(c00, c00, c01, c01);
        scoef[wid][pl][k][1] = make_float4(c10, c10, c11, c11);
        saddr[wid][pl][k] = make_int4((jy0*WW + jx0)*CC, (jy0*WW + jx1)*CC,
                                      (jy1*WW + jx0)*CC, (jy1*WW + jx1)*CC);
    }
    __syncwarp();

    int half = lane >> 4;
    int c4 = (lane & 15) * 4;
    int gp = gp0 + half;
    int b = gp / HWP;
    const float* sb = src + (size_t)b*HWP*CC + c4;

    ulonglong2 acc = *(const ulonglong2*)(bias + c4);

#pragma unroll
    for (int k = 0; k < K2; k++) {
        int4 ad = saddr[wid][half][k];
        ulonglong2 cA = *((const ulonglong2*)&scoef[wid][half][k][0]);
        ulonglong2 cB = *((const ulonglong2*)&scoef[wid][half][k][1]);
        ulonglong2 v00 = *(const ulonglong2*)(sb + ad.x);
        ulonglong2 v01 = *(const ulonglong2*)(sb + ad.y);
        ulonglong2 v10 = *(const ulonglong2*)(sb + ad.z);
        ulonglong2 v11 = *(const ulonglong2*)(sb + ad.w);
        ulonglong2 wv  = *(const ulonglong2*)(wt + k*CC + c4);
        unsigned long long t0 = mul2(cA.x, v00.x);
        t0 = fma2(cA.y, v01.x, t0);
        t0 = fma2(cB.x, v10.x, t0);
        t0 = fma2(cB.y, v11.x, t0);
        acc.x = fma2(wv.x, t0, acc.x);
        unsigned long long t1 = mul2(cA.x, v00.y);
        t1 = fma2(cA.y, v01.y, t1);
        t1 = fma2(cB.x, v10.y, t1);
        t1 = fma2(cB.y, v11.y, t1);
        acc.y = fma2(wv.y, t1, acc.y);
    }
    *(ulonglong2*)(out + (size_t)gp*CC + c4) = acc;
}

// ---------------- GAP partial sums (float4, 256 threads) ----------------
__global__ void k_gap_part() {
    int b = blockIdx.x >> 5;
    int chunk = blockIdx.x & 31;
    int q = threadIdx.x & 15;    // channel group (4 ch)
    int s = threadIdx.x >> 4;    // pixel stride slot
    float4 a1 = make_float4(0,0,0,0), a2 = make_float4(0,0,0,0);
    for (int p = s; p < 98; p += 16) {
        size_t base = ((size_t)(b*HWP) + chunk*98 + p)*CC + q*4;
        float4 v1 = *(const float4*)(g_out1 + base);
        float4 v2 = *(const float4*)(g_out2 + base);
        a1.x += v1.x; a1.y += v1.y; a1.z += v1.z; a1.w += v1.w;
        a2.x += v2.x; a2.y += v2.y; a2.z += v2.z; a2.w += v2.w;
    }
    __shared__ float4 sh1[16][16], sh2[16][16];
    sh1[s][q] = a1; sh2[s][q] = a2;
    __syncthreads();
    if (s == 0) {
#pragma unroll
        for (int j = 1; j < 16; j++) {
            float4 v1 = sh1[j][q], v2 = sh2[j][q];
            a1.x += v1.x; a1.y += v1.y; a1.z += v1.z; a1.w += v1.w;
            a2.x += v2.x; a2.y += v2.y; a2.z += v2.z; a2.w += v2.w;
        }
        *(float4*)(g_part1 + (b*32 + chunk)*CC + q*4) = a1;
        *(float4*)(g_part2 + (b*32 + chunk)*CC + q*4) = a2;
    }
}

// ---------------- GAP finalize + softmax attn ----------------
__global__ void k_gap_final() {
    int b = blockIdx.x;
    int c = threadIdx.x;
    float s1 = 0.f, s2 = 0.f;
    for (int j = 0; j < 32; j++) {
        s1 += g_part1[(b*32 + j)*CC + c];
        s2 += g_part2[(b*32 + j)*CC + c];
    }
    float g1 = s1 * (1.f/3136.f), g2 = s2 * (1.f/3136.f);
    float m = fmaxf(g1, g2);
    float e1 = expf(g1 - m), e2 = expf(g2 - m);
    g_attn[b*CC + c] = e1 / (e1 + e2);
}

// ---------------- combine + NHWC -> NCHW ----------------
__global__ void k_combine(float* __restrict__ out) {
    __shared__ float tile[CC][33];
    int b  = blockIdx.x / 98;
    int p0 = (blockIdx.x % 98) * 32;
    int tid = threadIdx.x;
    int c = tid & 63;
    float a = g_attn[b*CC + c];
#pragma unroll
    for (int it = 0; it < 8; it++) {
        int pp = (tid >> 6) + it*4;
        size_t idx = ((size_t)(b*HWP + p0 + pp))*CC + c;
        float v1 = g_out1[idx], v2 = g_out2[idx];
        tile[c][pp] = v1*a + v2*(1.f - a);
    }
    __syncthreads();
#pragma unroll
    for (int it = 0; it < 8; it++) {
        int idx = tid + it*256;
        int cc = idx >> 5, pp = idx & 31;
        out[((size_t)(b*CC + cc))*HWP + p0 + pp] = tile[cc][pp];
    }
}

// ---------------- launcher ----------------
extern "C" void kernel_launch(void* const* d_in, const int* in_sizes, int n_in,
                              void* d_out, int out_size) {
    const float* x      = (const float*)d_in[0];
    const float* w_off3 = (const float*)d_in[1];
    const float* b_off3 = (const float*)d_in[2];
    const float* w_off2 = (const float*)d_in[3];
    const float* b_off2 = (const float*)d_in[4];
    const float* w7     = (const float*)d_in[5];
    const float* b7     = (const float*)d_in[6];
    const float* w5     = (const float*)d_in[7];
    const float* b5     = (const float*)d_in[8];
    float* out = (float*)d_out;

    float *p_xcl, *p_off3, *p_off2, *p_out1, *p_out2, *p_w7t, *p_w5t;
    cudaGetSymbolAddress((void**)&p_xcl,  g_xcl);
    cudaGetSymbolAddress((void**)&p_off3, g_off3);
    cudaGetSymbolAddress((void**)&p_off2, g_off2);
    cudaGetSymbolAddress((void**)&p_out1, g_out1);
    cudaGetSymbolAddress((void**)&p_out2, g_out2);
    cudaGetSymbolAddress((void**)&p_w7t,  g_w7t);
    cudaGetSymbolAddress((void**)&p_w5t,  g_w5t);

    k_wprep<<<1, 256>>>(w7, w5, w_off3, b_off3, w_off2, b_off2);
    k_nchw2cl<<<BB*98, 256>>>(x);

    k_conv_fused<<<BB*HH*4, 96>>>(p_xcl, p_off3, p_off2);

    k_deform<7,9,3><<<NPIX/8, 128>>>(p_xcl,  p_off3, p_w7t, b7, p_out1);
    k_deform<5,6,3><<<NPIX/8, 128>>>(p_out1, p_off2, p_w5t, b5, p_out2);

    k_gap_part<<<BB*32, 256>>>();
    k_gap_final<<<BB, 64>>>();
    k_combine<<<BB*98, 256>>>(out);
}

// round 4
// speedup vs baseline: 2.2870x; 1.1372x over previous
#include <cuda_runtime.h>

#define HH 56
#define WW 56
#define CC 64
#define BB 4
#define HWP 3136           // 56*56
#define NPIX (BB*HWP)      // 12544

// ---------------- packed f32x2 helpers ----------------
__device__ __forceinline__ unsigned long long fma2(unsigned long long a, unsigned long long b, unsigned long long c) {
    unsigned long long d;
    asm("fma.rn.f32x2 %0, %1, %2, %3;" : "=l"(d) : "l"(a), "l"(b), "l"(c));
    return d;
}
__device__ __forceinline__ unsigned long long mul2(unsigned long long a, unsigned long long b) {
    unsigned long long d;
    asm("mul.rn.f32x2 %0, %1, %2;" : "=l"(d) : "l"(a), "l"(b));
    return d;
}

// ---------------- scratch (device globals; no allocations) ----------------
__device__ __align__(16) float g_xcl [NPIX*CC];      // x in NHWC
__device__ __align__(16) float g_off3[NPIX*98];      // offset3 [pix][98]
__device__ __align__(16) float g_off2[NPIX*50];      // offset2 [pix][50]
__device__ __align__(16) float g_out1[NPIX*CC];      // out1 NHWC
__device__ __align__(16) float g_out2[NPIX*CC];      // out2 NHWC
__device__ __align__(16) float g_w7t [49*CC];        // w7 transposed [k][c]
__device__ __align__(16) float g_w5t [25*CC];        // w5 transposed [k][c]
__device__ __align__(16) float2 g_wp3[288*49];       // conv3 weight pairs [(ic*9+j)][o]
__device__ __align__(16) float2 g_wp2[288*25];       // conv2 weight pairs
__device__ __align__(16) float2 g_bp3[49];
__device__ __align__(16) float2 g_bp2[25];
__device__ __align__(16) float g_part1[BB*32*CC];
__device__ __align__(16) float g_part2[BB*32*CC];
__device__ __align__(16) float g_attn [BB*CC];

// ---------------- weight prep (grid-parallel) ----------------
__global__ void k_wprep(const float* __restrict__ w7, const float* __restrict__ w5,
                        const float* __restrict__ w_off3, const float* __restrict__ b_off3,
                        const float* __restrict__ w_off2, const float* __restrict__ b_off2) {
    int tid = blockIdx.x * blockDim.x + threadIdx.x;
    int nthr = gridDim.x * blockDim.x;
    for (int i = tid; i < CC*49; i += nthr) {
        int c = i / 49, k = i - c*49;
        g_w7t[k*CC + c] = w7[i];
    }
    for (int i = tid; i < CC*25; i += nthr) {
        int c = i / 25, k = i - c*25;
        g_w5t[k*CC + c] = w5[i];
    }
    for (int i = tid; i < 288*49; i += nthr) {
        int r = i / 49, o = i - r*49;
        int ic = r / 9, j = r - ic*9;
        g_wp3[i] = make_float2(w_off3[(o*32 + ic)*9 + j], w_off3[((o+49)*32 + ic)*9 + j]);
    }
    for (int i = tid; i < 288*25; i += nthr) {
        int r = i / 25, o = i - r*25;
        int ic = r / 9, j = r - ic*9;
        g_wp2[i] = make_float2(w_off2[(o*32 + ic)*9 + j], w_off2[((o+25)*32 + ic)*9 + j]);
    }
    if (tid < 49) g_bp3[tid] = make_float2(b_off3[tid], b_off3[tid+49]);
    if (tid >= 64 && tid < 89) g_bp2[tid-64] = make_float2(b_off2[tid-64], b_off2[tid-64+25]);
}

// ---------------- NCHW -> NHWC transpose of x ----------------
__global__ void k_nchw2cl(const float* __restrict__ x) {
    __shared__ float tile[CC][33];
    int b  = blockIdx.x / 98;
    int p0 = (blockIdx.x % 98) * 32;
    int tid = threadIdx.x;
#pragma unroll
    for (int it = 0; it < 8; it++) {
        int idx = tid + it*256;
        int c = idx >> 5, pp = idx & 31;
        tile[c][pp] = x[((size_t)(b*CC + c))*HWP + p0 + pp];
    }
    __syncthreads();
    int c2 = tid & 63;
#pragma unroll
    for (int it = 0; it < 8; it++) {
        int pp2 = (tid >> 6) + it*4;
        g_xcl[((size_t)(b*HWP + p0 + pp2))*CC + c2] = tile[c2][pp2];
    }
}

// ---------------- fused grouped 3x3 convs, channel-pair f32x2 -------------
__global__ __launch_bounds__(96) void k_conv_fused(const float* __restrict__ xcl,
                                                   float* __restrict__ out3,
                                                   float* __restrict__ out2) {
    __shared__ float2 xsp[3][16][32];   // [dy][col][ic]: (x[ic], x[ic+32])
    int bid = blockIdx.x;
    int xt = bid & 3;
    int y  = (bid >> 2) % HH;
    int b  = bid / (4*HH);
    int x0 = xt * 14;
    int tid = threadIdx.x;

#pragma unroll
    for (int it = 0; it < 16; it++) {
        int i = tid + it*96;
        int ic  = i & 31;
        int col = (i >> 5) & 15;
        int dy  = i >> 9;
        int yy = y + dy - 1;
        int xx = x0 + col - 1;
        float v0 = 0.f, v1 = 0.f;
        if (yy >= 0 && yy < HH && xx >= 0 && xx < WW) {
            size_t base = ((size_t)((b*HH + yy)*WW + xx))*CC;
            v0 = xcl[base + ic];
            v1 = xcl[base + 32 + ic];
        }
        xsp[dy][col][ic] = make_float2(v0, v1);
    }
    __syncthreads();

    int t = tid;
    if (t < 74) {
        bool is3 = (t < 49);
        int o = is3 ? t : t - 49;
        int stride = is3 ? 49 : 25;
        const unsigned long long* wrow = is3 ? ((const unsigned long long*)g_wp3) + o
                                             : ((const unsigned long long*)g_wp2) + o;
        float2 bp = is3 ? g_bp3[o] : g_bp2[o];
        unsigned long long bdup;
        asm("mov.b64 %0, {%1, %2};" : "=l"(bdup) : "f"(bp.x), "f"(bp.y));

        unsigned long long acc[14];
#pragma unroll
        for (int p = 0; p < 14; p++) acc[p] = bdup;

#pragma unroll 2
        for (int ic = 0; ic < 32; ic++) {
            unsigned long long w2[9];
#pragma unroll
            for (int j = 0; j < 9; j++)
                w2[j] = wrow[(ic*9 + j)*stride];
#pragma unroll
            for (int dy = 0; dy < 3; dy++) {
                unsigned long long xm[16];
#pragma unroll
                for (int col = 0; col < 16; col++)
                    xm[col] = *(const unsigned long long*)&xsp[dy][col][ic];
#pragma unroll
                for (int dx = 0; dx < 3; dx++) {
                    unsigned long long wv = w2[dy*3 + dx];
#pragma unroll
                    for (int p = 0; p < 14; p++)
                        acc[p] = fma2(wv, xm[p+dx], acc[p]);
                }
            }
        }

        size_t pix = (size_t)(b*HH + y)*WW + x0;
        union { unsigned long long u; float f[2]; } cv;
        if (is3) {
#pragma unroll
            for (int p = 0; p < 14; p++) {
                cv.u = acc[p];
                out3[(pix + p)*98 + o]      = cv.f[0];
                out3[(pix + p)*98 + o + 49] = cv.f[1];
            }
        } else {
#pragma unroll
            for (int p = 0; p < 14; p++) {
                cv.u = acc[p];
                out2[(pix + p)*50 + o]      = cv.f[0];
                out2[(pix + p)*50 + o + 25] = cv.f[1];
            }
        }
    }
}

// ---------------- deformable depthwise conv (software-pipelined) ----------
// 128 threads = 4 warps; each warp owns TWO pixels (half-warp each);
// lane owns 4 channels. Gather LDGs for tap k+1 prefetched while computing k.
template<int K, int PAD, int DIL>
__global__ __launch_bounds__(128) void k_deform(
                         const float* __restrict__ src,   // NHWC
                         const float* __restrict__ off,   // [pix][2*K*K]
                         const float* __restrict__ wt,    // [K*K][C]
                         const float* __restrict__ bias,
                         float* __restrict__ out) {       // NHWC
    constexpr int K2 = K*K;
    constexpr int OFFC = 2*K2;
    __shared__ float4 scoef[4][2][K2][2];  // {c00,c00,c01,c01},{c10,c10,c11,c11}
    __shared__ int4   saddr[4][2][K2];
    int wid  = threadIdx.x >> 5;
    int lane = threadIdx.x & 31;
    int gp0 = blockIdx.x*8 + wid*2;

    // phase 1: per-tap coefficient + address precompute for both pixels
    for (int tpos = lane; tpos < 2*K2; tpos += 32) {
        int pl = tpos / K2;
        int k  = tpos - pl*K2;
        int gp = gp0 + pl;
        int b = gp / HWP;
        int p = gp - b*HWP;
        int y = p / WW;
        int x = p - y*WW;
        float2 o2 = *(const float2*)(off + (size_t)gp*OFFC + 2*k);
        int ky = k / K, kx = k - ky*K;
        float py = (float)(y - PAD + DIL*ky) + o2.x;
        float px = (float)(x - PAD + DIL*kx) + o2.y;
        float fy = floorf(py), fx = floorf(px);
        float ly = py - fy,  lx = px - fx;
        float hy = 1.f - ly, hx = 1.f - lx;
        int iy0 = (int)fy, ix0 = (int)fx;
        int iy1 = iy0 + 1, ix1 = ix0 + 1;
        bool vy0 = (unsigned)iy0 < HH;
        bool vy1 = (unsigned)iy1 < HH;
        bool vx0 = (unsigned)ix0 < WW;
        bool vx1 = (unsigned)ix1 < WW;
        float c00 = (vy0 && vx0) ? hy*hx : 0.f;
        float c01 = (vy0 && vx1) ? hy*lx : 0.f;
        float c10 = (vy1 && vx0) ? ly*hx : 0.f;
        float c11 = (vy1 && vx1) ? ly*lx : 0.f;
        int jy0 = min(max(iy0,0), HH-1), jy1 = min(max(iy1,0), HH-1);
        int jx0 = min(max(ix0,0), WW-1), jx1 = min(max(ix1,0), WW-1);
        scoef[wid][pl][k][0] = make_float4(c00, c00, c01, c01);
        scoef[wid][pl][k][1] = make_float4(c10, c10, c11, c11);
        saddr[wid][pl][k] = make_int4((jy0*WW + jx0)*CC, (jy0*WW + jx1)*CC,
                                      (jy1*WW + jx0)*CC, (jy1*WW + jx1)*CC);
    }
    __syncwarp();

    int half = lane >> 4;
    int c4 = (lane & 15) * 4;
    int gp = gp0 + half;
    int b = gp / HWP;
    const float* sb = src + (size_t)b*HWP*CC + c4;
    const float* wp = wt + c4;

    ulonglong2 acc = *(const ulonglong2*)(bias + c4);

    // double-buffered gather values
    ulonglong2 v00[2], v01[2], v10[2], v11[2], wv[2];

    {   // prologue: load tap 0 into buffer 0
        int4 ad = saddr[wid][half][0];
        v00[0] = *(const ulonglong2*)(sb + ad.x);
        v01[0] = *(const ulonglong2*)(sb + ad.y);
        v10[0] = *(const ulonglong2*)(sb + ad.z);
        v11[0] = *(const ulonglong2*)(sb + ad.w);
        wv[0]  = *(const ulonglong2*)(wp);
    }

#pragma unroll
    for (int k = 0; k < K2; k++) {
        int s = k & 1;
        if (k + 1 < K2) {   // prefetch next tap into other buffer
            int ns = s ^ 1;
            int4 ad = saddr[wid][half][k+1];
            v00[ns] = *(const ulonglong2*)(sb + ad.x);
            v01[ns] = *(const ulonglong2*)(sb + ad.y);
            v10[ns] = *(const ulonglong2*)(sb + ad.z);
            v11[ns] = *(const ulonglong2*)(sb + ad.w);
            wv[ns]  = *(const ulonglong2*)(wp + (k+1)*CC);
        }
        ulonglong2 cA = *((const ulonglong2*)&scoef[wid][half][k][0]);
        ulonglong2 cB = *((const ulonglong2*)&scoef[wid][half][k][1]);
        unsigned long long t0 = mul2(cA.x, v00[s].x);
        t0 = fma2(cA.y, v01[s].x, t0);
        t0 = fma2(cB.x, v10[s].x, t0);
        t0 = fma2(cB.y, v11[s].x, t0);
        acc.x = fma2(wv[s].x, t0, acc.x);
        unsigned long long t1 = mul2(cA.x, v00[s].y);
        t1 = fma2(cA.y, v01[s].y, t1);
        t1 = fma2(cB.x, v10[s].y, t1);
        t1 = fma2(cB.y, v11[s].y, t1);
        acc.y = fma2(wv[s].y, t1, acc.y);
    }
    *(ulonglong2*)(out + (size_t)gp*CC + c4) = acc;
}

// ---------------- GAP partial sums (float4, 256 threads) ----------------
__global__ void k_gap_part() {
    int b = blockIdx.x >> 5;
    int chunk = blockIdx.x & 31;
    int q = threadIdx.x & 15;
    int s = threadIdx.x >> 4;
    float4 a1 = make_float4(0,0,0,0), a2 = make_float4(0,0,0,0);
    for (int p = s; p < 98; p += 16) {
        size_t base = ((size_t)(b*HWP) + chunk*98 + p)*CC + q*4;
        float4 v1 = *(const float4*)(g_out1 + base);
        float4 v2 = *(const float4*)(g_out2 + base);
        a1.x += v1.x; a1.y += v1.y; a1.z += v1.z; a1.w += v1.w;
        a2.x += v2.x; a2.y += v2.y; a2.z += v2.z; a2.w += v2.w;
    }
    __shared__ float4 sh1[16][16], sh2[16][16];
    sh1[s][q] = a1; sh2[s][q] = a2;
    __syncthreads();
    if (s == 0) {
#pragma unroll
        for (int j = 1; j < 16; j++) {
            float4 v1 = sh1[j][q], v2 = sh2[j][q];
            a1.x += v1.x; a1.y += v1.y; a1.z += v1.z; a1.w += v1.w;
            a2.x += v2.x; a2.y += v2.y; a2.z += v2.z; a2.w += v2.w;
        }
        *(float4*)(g_part1 + (b*32 + chunk)*CC + q*4) = a1;
        *(float4*)(g_part2 + (b*32 + chunk)*CC + q*4) = a2;
    }
}

// ---------------- GAP finalize + softmax attn ----------------
__global__ void k_gap_final() {
    int b = blockIdx.x;
    int c = threadIdx.x;
    float s1 = 0.f, s2 = 0.f;
    for (int j = 0; j < 32; j++) {
        s1 += g_part1[(b*32 + j)*CC + c];
        s2 += g_part2[(b*32 + j)*CC + c];
    }
    float g1 = s1 * (1.f/3136.f), g2 = s2 * (1.f/3136.f);
    float m = fmaxf(g1, g2);
    float e1 = expf(g1 - m), e2 = expf(g2 - m);
    g_attn[b*CC + c] = e1 / (e1 + e2);
}

// ---------------- combine + NHWC -> NCHW ----------------
__global__ void k_combine(float* __restrict__ out) {
    __shared__ float tile[CC][33];
    int b  = blockIdx.x / 98;
    int p0 = (blockIdx.x % 98) * 32;
    int tid = threadIdx.x;
    int c = tid & 63;
    float a = g_attn[b*CC + c];
#pragma unroll
    for (int it = 0; it < 8; it++) {
        int pp = (tid >> 6) + it*4;
        size_t idx = ((size_t)(b*HWP + p0 + pp))*CC + c;
        float v1 = g_out1[idx], v2 = g_out2[idx];
        tile[c][pp] = v1*a + v2*(1.f - a);
    }
    __syncthreads();
#pragma unroll
    for (int it = 0; it < 8; it++) {
        int idx = tid + it*256;
        int cc = idx >> 5, pp = idx & 31;
        out[((size_t)(b*CC + cc))*HWP + p0 + pp] = tile[cc][pp];
    }
}

// ---------------- launcher ----------------
extern "C" void kernel_launch(void* const* d_in, const int* in_sizes, int n_in,
                              void* d_out, int out_size) {
    const float* x      = (const float*)d_in[0];
    const float* w_off3 = (const float*)d_in[1];
    const float* b_off3 = (const float*)d_in[2];
    const float* w_off2 = (const float*)d_in[3];
    const float* b_off2 = (const float*)d_in[4];
    const float* w7     = (const float*)d_in[5];
    const float* b7     = (const float*)d_in[6];
    const float* w5     = (const float*)d_in[7];
    const float* b5     = (const float*)d_in[8];
    float* out = (float*)d_out;

    float *p_xcl, *p_off3, *p_off2, *p_out1, *p_out2, *p_w7t, *p_w5t;
    cudaGetSymbolAddress((void**)&p_xcl,  g_xcl);
    cudaGetSymbolAddress((void**)&p_off3, g_off3);
    cudaGetSymbolAddress((void**)&p_off2, g_off2);
    cudaGetSymbolAddress((void**)&p_out1, g_out1);
    cudaGetSymbolAddress((void**)&p_out2, g_out2);
    cudaGetSymbolAddress((void**)&p_w7t,  g_w7t);
    cudaGetSymbolAddress((void**)&p_w5t,  g_w5t);

    k_wprep<<<64, 256>>>(w7, w5, w_off3, b_off3, w_off2, b_off2);
    k_nchw2cl<<<BB*98, 256>>>(x);

    k_conv_fused<<<BB*HH*4, 96>>>(p_xcl, p_off3, p_off2);

    k_deform<7,9,3><<<NPIX/8, 128>>>(p_xcl,  p_off3, p_w7t, b7, p_out1);
    k_deform<5,6,3><<<NPIX/8, 128>>>(p_out1, p_off2, p_w5t, b5, p_out2);

    k_gap_part<<<BB*32, 256>>>();
    k_gap_final<<<BB, 64>>>();
    k_combine<<<BB*98, 256>>>(out);
}